// round 3
// baseline (speedup 1.0000x reference)
#include <cuda_runtime.h>
#include <cuda_bf16.h>

#define D_IN   128
#define D_OUT  64
#define MAX_NODES 65536      // padded (>= nchunks*1024)
#define MAX_EDGES 1048576
#define CHUNK 1024

// Scratch (device globals; no allocations allowed)
__device__ float g_h[(size_t)MAX_NODES * D_OUT];
__device__ int   g_cnt[MAX_NODES];
__device__ int   g_row_ptr[MAX_NODES];
__device__ int   g_fill_ptr[MAX_NODES];
__device__ int   g_adj[MAX_EDGES];
__device__ int   g_chunk_base[256];

// ---------------------------------------------------------------------------
// f32x2 packed helpers
// ---------------------------------------------------------------------------
__device__ __forceinline__ unsigned long long pk2(float a, float b) {
    unsigned long long r;
    asm("mov.b64 %0, {%1, %2};" : "=l"(r) : "f"(a), "f"(b));
    return r;
}
__device__ __forceinline__ void ffma2(unsigned long long& d,
                                      unsigned long long a,
                                      unsigned long long b) {
    asm("fma.rn.f32x2 %0, %1, %2, %3;" : "=l"(d) : "l"(a), "l"(b), "l"(d));
}
__device__ __forceinline__ float2 upk2(unsigned long long v) {
    float2 f;
    asm("mov.b64 {%0, %1}, %2;" : "=f"(f.x), "=f"(f.y) : "l"(v));
    return f;
}

// ---------------------------------------------------------------------------
// K0: zero histogram counters (padded so int4 paths need no guards)
// ---------------------------------------------------------------------------
__global__ void zero_cnt_kernel(int npad) {
    int i = blockIdx.x * blockDim.x + threadIdx.x;
    if (i < npad) g_cnt[i] = 0;
}

// ---------------------------------------------------------------------------
// K1: in-degree histogram
// ---------------------------------------------------------------------------
__global__ void hist_kernel(const int* __restrict__ row, int E) {
    int e = blockIdx.x * blockDim.x + threadIdx.x;
    if (e < E) atomicAdd(&g_cnt[__ldg(&row[e])], 1);
}

// ---------------------------------------------------------------------------
// K2a: per-chunk sums (256 threads x int4 = 1024 counts per block)
// ---------------------------------------------------------------------------
__global__ void __launch_bounds__(256) chunk_sum_kernel() {
    __shared__ int wsum[8];
    int tid = threadIdx.x, lane = tid & 31, w = tid >> 5;
    int base = blockIdx.x * CHUNK + tid * 4;
    int4 v = *(const int4*)&g_cnt[base];
    int s = v.x + v.y + v.z + v.w;
#pragma unroll
    for (int off = 16; off > 0; off >>= 1) s += __shfl_down_sync(~0u, s, off);
    if (lane == 0) wsum[w] = s;
    __syncthreads();
    if (tid == 0) {
        int t = 0;
#pragma unroll
        for (int i = 0; i < 8; i++) t += wsum[i];
        g_chunk_base[blockIdx.x] = t;
    }
}

// ---------------------------------------------------------------------------
// K2b: exclusive scan of chunk sums (single block, 64 threads, nchunks<=64)
// ---------------------------------------------------------------------------
__global__ void __launch_bounds__(64) scan_partials_kernel(int nchunks) {
    __shared__ int w0sum;
    int tid = threadIdx.x, lane = tid & 31, w = tid >> 5;
    int v = (tid < nchunks) ? g_chunk_base[tid] : 0;
    int x = v;
#pragma unroll
    for (int off = 1; off < 32; off <<= 1) {
        int t = __shfl_up_sync(~0u, x, off);
        if (lane >= off) x += t;
    }
    if (w == 0 && lane == 31) w0sum = x;
    __syncthreads();
    if (w == 1) x += w0sum;
    if (tid < nchunks) g_chunk_base[tid] = x - v;   // exclusive
}

// ---------------------------------------------------------------------------
// K2c: per-chunk exclusive scan + base (shuffle scan; 4 elems/thread)
// ---------------------------------------------------------------------------
__global__ void __launch_bounds__(256) scan_chunk_kernel() {
    __shared__ int wsum[8];
    int tid = threadIdx.x, lane = tid & 31, w = tid >> 5;
    int base = blockIdx.x * CHUNK + tid * 4;
    int4 v = *(const int4*)&g_cnt[base];
    int tsum = v.x + v.y + v.z + v.w;

    int inc = tsum;
#pragma unroll
    for (int off = 1; off < 32; off <<= 1) {
        int t = __shfl_up_sync(~0u, inc, off);
        if (lane >= off) inc += t;
    }
    if (lane == 31) wsum[w] = inc;
    __syncthreads();
    if (w == 0 && lane < 8) {
        int x = wsum[lane];
#pragma unroll
        for (int off = 1; off < 8; off <<= 1) {
            int t = __shfl_up_sync(0xff, x, off);
            if (lane >= off) x += t;
        }
        wsum[lane] = x;   // inclusive per-warp prefix
    }
    __syncthreads();

    int prefix = (w > 0 ? wsum[w - 1] : 0) + (inc - tsum);
    int e0 = g_chunk_base[blockIdx.x] + prefix;
    int e1 = e0 + v.x, e2 = e1 + v.y, e3 = e2 + v.z;
    int4 ev = make_int4(e0, e1, e2, e3);
    *(int4*)&g_row_ptr[base]  = ev;
    *(int4*)&g_fill_ptr[base] = ev;
}

// ---------------------------------------------------------------------------
// K3: fill adjacency
// ---------------------------------------------------------------------------
__global__ void fill_kernel(const int* __restrict__ row,
                            const int* __restrict__ col, int E) {
    int e = blockIdx.x * blockDim.x + threadIdx.x;
    if (e >= E) return;
    int r = __ldg(&row[e]);
    int pos = atomicAdd(&g_fill_ptr[r], 1);
    g_adj[pos] = __ldg(&col[e]);
}

// ---------------------------------------------------------------------------
// K4: GEMM h = x @ W^T + b with packed f32x2 FMA over k-parity.
// 128 threads, 64 nodes x 64 outs per block, thread tile 8 nodes x 4 outs.
// acc[i][j] is f32x2 = (sum over even k, sum over odd k); final lo+hi.
// ---------------------------------------------------------------------------
__global__ void __launch_bounds__(128) gemm_kernel(
    const float* __restrict__ x, const float* __restrict__ W,
    const float* __restrict__ b, int N)
{
    __shared__ float4 xs[64][33];
    __shared__ float4 ws[64][33];

    const int tid = threadIdx.x;
    const int nb  = blockIdx.x * 64;

    const float4* W4 = (const float4*)W;
#pragma unroll
    for (int i = 0; i < 16; i++) {
        int lin = tid + 128 * i;
        int r = lin >> 5, c = lin & 31;
        ws[r][c] = W4[lin];
    }
    const float4* x4 = (const float4*)x;
#pragma unroll
    for (int i = 0; i < 16; i++) {
        int lin = tid + 128 * i;
        int r = lin >> 5, c = lin & 31;
        int node = nb + r;
        float4 v = make_float4(0.f, 0.f, 0.f, 0.f);
        if (node < N) v = x4[node * 32 + c];
        xs[r][c] = v;
    }
    __syncthreads();

    const int tx = tid & 15;
    const int ty = tid >> 4;

    unsigned long long acc[8][4];
#pragma unroll
    for (int i = 0; i < 8; i++)
#pragma unroll
        for (int j = 0; j < 4; j++) acc[i][j] = 0ull;

#pragma unroll 4
    for (int k = 0; k < 32; k++) {
        unsigned long long xlo[8], xhi[8], wlo[4], whi[4];
#pragma unroll
        for (int i = 0; i < 8; i++) {
            float4 v = xs[ty + 8 * i][k];
            xlo[i] = pk2(v.x, v.y);
            xhi[i] = pk2(v.z, v.w);
        }
#pragma unroll
        for (int j = 0; j < 4; j++) {
            float4 v = ws[tx + 16 * j][k];
            wlo[j] = pk2(v.x, v.y);
            whi[j] = pk2(v.z, v.w);
        }
#pragma unroll
        for (int i = 0; i < 8; i++) {
#pragma unroll
            for (int j = 0; j < 4; j++) {
                ffma2(acc[i][j], xlo[i], wlo[j]);
                ffma2(acc[i][j], xhi[i], whi[j]);
            }
        }
    }

    float bias[4];
#pragma unroll
    for (int j = 0; j < 4; j++) bias[j] = __ldg(&b[tx + 16 * j]);

#pragma unroll
    for (int i = 0; i < 8; i++) {
        int node = nb + ty + 8 * i;
        if (node < N) {
#pragma unroll
            for (int j = 0; j < 4; j++) {
                float2 p = upk2(acc[i][j]);
                g_h[(size_t)node * D_OUT + tx + 16 * j] = p.x + p.y + bias[j];
            }
        }
    }
}

// ---------------------------------------------------------------------------
// K5: aggregate + normalize. One warp per node; each lane owns one float2
// (2 of the 64 output dims). Uniform loop length per warp (no divergence).
// ---------------------------------------------------------------------------
__global__ void __launch_bounds__(256) aggregate_kernel(float* __restrict__ out, int N)
{
    int warp = (blockIdx.x * blockDim.x + threadIdx.x) >> 5;
    int lane = threadIdx.x & 31;
    if (warp >= N) return;

    int start = __ldg(&g_row_ptr[warp]);
    int deg   = __ldg(&g_cnt[warp]);

    const float2* h2 = (const float2*)g_h;
    float2 acc = make_float2(0.f, 0.f);

    int j = 0;
    for (; j + 4 <= deg; j += 4) {
        int c0 = __ldg(&g_adj[start + j]);
        int c1 = __ldg(&g_adj[start + j + 1]);
        int c2 = __ldg(&g_adj[start + j + 2]);
        int c3 = __ldg(&g_adj[start + j + 3]);
        float2 a0 = h2[c0 * 32 + lane];
        float2 a1 = h2[c1 * 32 + lane];
        float2 a2 = h2[c2 * 32 + lane];
        float2 a3 = h2[c3 * 32 + lane];
        acc.x += (a0.x + a1.x) + (a2.x + a3.x);
        acc.y += (a0.y + a1.y) + (a2.y + a3.y);
    }
    for (; j < deg; j++) {
        int c = __ldg(&g_adj[start + j]);
        float2 a = h2[c * 32 + lane];
        acc.x += a.x; acc.y += a.y;
    }

    float s = 1.0f / fmaxf((float)deg, 1.0f);
    acc.x *= s; acc.y *= s;
    ((float2*)out)[warp * 32 + lane] = acc;
}

// ---------------------------------------------------------------------------
extern "C" void kernel_launch(void* const* d_in, const int* in_sizes, int n_in,
                              void* d_out, int out_size)
{
    const float* x   = (const float*)d_in[0];
    const float* W   = (const float*)d_in[1];
    const float* b   = (const float*)d_in[2];
    const int*   row = (const int*)d_in[3];
    const int*   col = (const int*)d_in[4];
    float* out = (float*)d_out;

    int N = in_sizes[0] / D_IN;   // 50000
    int E = in_sizes[3];          // 800000

    int nchunks = (N + CHUNK - 1) / CHUNK;   // 49
    int npad = nchunks * CHUNK;              // 50176

    zero_cnt_kernel<<<(npad + 255) / 256, 256>>>(npad);
    hist_kernel<<<(E + 255) / 256, 256>>>(row, E);
    chunk_sum_kernel<<<nchunks, 256>>>();
    scan_partials_kernel<<<1, 64>>>(nchunks);
    scan_chunk_kernel<<<nchunks, 256>>>();
    fill_kernel<<<(E + 255) / 256, 256>>>(row, col, E);
    gemm_kernel<<<(N + 63) / 64, 128>>>(x, W, b, N);

    long long total = (long long)N * 32;
    aggregate_kernel<<<(int)((total + 255) / 256), 256>>>(out, N);
}